// round 8
// baseline (speedup 1.0000x reference)
#include <cuda_runtime.h>
#include <math.h>

#define BATCH   8192
#define NNODES  32
#define DIM     128
#define KDIM    384    // 3*128

// ---- scratch (no allocation allowed) ----
__device__ float g_G[BATCH * KDIM];       // (B, 3*128) weighted feature sums
__device__ float g_wab[12 * DIM];         // rows 0..8: wtop[i*3+j], rows 9..11: wbot[j]
__device__ float g_wb01[2 * DIM];         // interleaved (wbot0[d], wbot1[d]) pairs
__device__ int   g_mask_mode;             // 0=bool/u8, 1=int32, 2=float32

__device__ __forceinline__ float2 ffma2(float2 a, float2 b, float2 c) {
    float2 d;
    asm("{\n\t"
        ".reg .b64 ra, rb, rc, rd;\n\t"
        "mov.b64 ra, {%2,%3};\n\t"
        "mov.b64 rb, {%4,%5};\n\t"
        "mov.b64 rc, {%6,%7};\n\t"
        "fma.rn.f32x2 rd, ra, rb, rc;\n\t"
        "mov.b64 {%0,%1}, rd;\n\t"
        "}"
        : "=f"(d.x), "=f"(d.y)
        : "f"(a.x), "f"(a.y), "f"(b.x), "f"(b.y), "f"(c.x), "f"(c.y));
    return d;
}

// ============================================================
// Kernel 0: blocks 0..11 = weight prep, block 12 = mask sniff
// ============================================================
__global__ __launch_bounds__(256) void prep_detect_kernel(const unsigned int* __restrict__ m,
                                                          const float* __restrict__ W,
                                                          const float* __restrict__ a) {
    if (blockIdx.x == 12) {
        __shared__ int sF, sG;
        if (threadIdx.x == 0) { sF = 0; sG = 0; }
        __syncthreads();
        int f = 0, g = 0;
        #pragma unroll
        for (int r = 0; r < 8; r++) {
            unsigned v = m[r * 256 + threadIdx.x];
            if (v == 0x3F800000u) f = 1;
            else if (v > 1u)      g = 1;
        }
        if (f) atomicOr(&sF, 1);
        if (g) atomicOr(&sG, 1);
        __syncthreads();
        if (threadIdx.x == 0) g_mask_mode = sF ? 2 : (sG ? 0 : 1);
        return;
    }

    const int i    = blockIdx.x >> 2;
    const int quar = blockIdx.x & 3;
    const int wid  = threadIdx.x >> 5;
    const int lane = threadIdx.x & 31;

    const float4 at0 = *(const float4*)&a[0 * 256 + lane * 4];
    const float4 at1 = *(const float4*)&a[1 * 256 + lane * 4];
    const float4 at2 = *(const float4*)&a[2 * 256 + lane * 4];
    const float4 ab  = *(const float4*)&a[i * 256 + 128 + lane * 4];

    float4 wv[4];
    #pragma unroll
    for (int r = 0; r < 4; r++) {
        int d = quar * 32 + r * 8 + wid;
        wv[r] = *(const float4*)&W[(size_t)i * (DIM * DIM) + (size_t)d * DIM + lane * 4];
    }

    #pragma unroll
    for (int r = 0; r < 4; r++) {
        int d = quar * 32 + r * 8 + wid;
        float4 x = wv[r];
        float s0 = x.x * at0.x + x.y * at0.y + x.z * at0.z + x.w * at0.w;
        float s1 = x.x * at1.x + x.y * at1.y + x.z * at1.z + x.w * at1.w;
        float s2 = x.x * at2.x + x.y * at2.y + x.z * at2.z + x.w * at2.w;
        float sb = x.x * ab.x  + x.y * ab.y  + x.z * ab.z  + x.w * ab.w;
        #pragma unroll
        for (int off = 16; off > 0; off >>= 1) {
            s0 += __shfl_xor_sync(0xFFFFFFFFu, s0, off);
            s1 += __shfl_xor_sync(0xFFFFFFFFu, s1, off);
            s2 += __shfl_xor_sync(0xFFFFFFFFu, s2, off);
            sb += __shfl_xor_sync(0xFFFFFFFFu, sb, off);
        }
        if (lane == 0) {
            g_wab[(i * 3 + 0) * DIM + d] = s0;
            g_wab[(i * 3 + 1) * DIM + d] = s1;
            g_wab[(i * 3 + 2) * DIM + d] = s2;
            g_wab[(9 + i) * DIM + d]     = sb;
            if (i == 0)      g_wb01[2 * d]     = sb;
            else if (i == 1) g_wb01[2 * d + 1] = sb;
        }
    }
}

// ============================================================
// Kernel 1: attention -> G.  128 threads = 1 batch, grid 8192.
//   h stays in registers; final reduction via float4 path.
// ============================================================
__global__ __launch_bounds__(128, 6) void attn_kernel(const float* __restrict__ hptr,
                                                      const void*  __restrict__ maskp) {
    __shared__ float h0_sh[DIM];            // node-0 features (self logits)
    __shared__ float sb8_sh[3][32][8];      // 8-lane partial sums per (j,node)
    __shared__ float E_sh[3];
    __shared__ float mk_sh[3][32];
    __shared__ float4 w2n_sh[32];           // (w2_0, w2_1, w2_2, pad) per node
    __shared__ float part_sh[4][3][DIM];    // per-warp partial G

    const int t    = threadIdx.x;
    const int w    = t >> 5;
    const int lane = t & 31;
    const int b    = blockIdx.x;

    const float4 wpA = *(const float4*)&g_wb01[lane * 8];
    const float4 wpB = *(const float4*)&g_wb01[lane * 8 + 4];
    const float4 wb2 = *(const float4*)&g_wab[11 * DIM + lane * 4];

    const float4* hp = (const float4*)(hptr + (size_t)b * (NNODES * DIM));
    float4 xs[8];
    #pragma unroll
    for (int v = 0; v < 8; v++) xs[v] = hp[v * 128 + t];

    if (t < 96) {
        int j = t >> 5, node = t & 31;
        size_t idx = (size_t)j * (BATCH * NNODES) + (size_t)b * NNODES + node;
        int mode = g_mask_mode;
        float mv;
        if (mode == 0)      mv = ((const unsigned char*)maskp)[idx] ? 1.f : 0.f;
        else if (mode == 1) mv = ((const int*)maskp)[idx] ? 1.f : 0.f;
        else                mv = (((const float*)maskp)[idx] != 0.f) ? 1.f : 0.f;
        mk_sh[j][node] = mv;
    }

    // ---- neighbor logit partials (reduce to 8-lane classes) ----
    #pragma unroll
    for (int v = 0; v < 8; v++) {
        float4 x = xs[v];
        int node = v * 4 + w;
        if (v == 0 && w == 0)
            *(float4*)&h0_sh[lane * 4] = x;

        float2 d01 = make_float2(0.f, 0.f);
        d01 = ffma2(make_float2(x.x, x.x), make_float2(wpA.x, wpA.y), d01);
        d01 = ffma2(make_float2(x.y, x.y), make_float2(wpA.z, wpA.w), d01);
        d01 = ffma2(make_float2(x.z, x.z), make_float2(wpB.x, wpB.y), d01);
        d01 = ffma2(make_float2(x.w, x.w), make_float2(wpB.z, wpB.w), d01);
        float d2 = x.x * wb2.x + x.y * wb2.y + x.z * wb2.z + x.w * wb2.w;
        #pragma unroll
        for (int off = 16; off >= 8; off >>= 1) {
            d01.x += __shfl_xor_sync(0xFFFFFFFFu, d01.x, off);
            d01.y += __shfl_xor_sync(0xFFFFFFFFu, d01.y, off);
            d2    += __shfl_xor_sync(0xFFFFFFFFu, d2,    off);
        }
        if (lane < 8 && node > 0) {
            sb8_sh[0][node][lane] = d01.x;
            sb8_sh[1][node][lane] = d01.y;
            sb8_sh[2][node][lane] = d2;
        }
    }
    __syncthreads();

    // ---- phase B ----
    int   jj[2], nd[2];
    bool  act[2];
    float pv[2];
    float Sreg[3] = {0.f, 0.f, 0.f};

    if (w < 2) {
        const int NN   = (w == 0) ? 15 : 16;
        const int base = (w == 0) ? 1  : 16;
        const int NP   = 3 * NN;

        float sbv[2];
        float lm = -INFINITY;
        #pragma unroll
        for (int r = 0; r < 2; r++) {
            int p = lane + r * 32;
            bool valid = (p < NP);
            int j = valid ? (p / NN) : 0;
            int node = valid ? (base + p % NN) : base;
            jj[r] = j; nd[r] = node;
            float4 sA = *(const float4*)&sb8_sh[j][node][0];
            float4 sB = *(const float4*)&sb8_sh[j][node][4];
            sbv[r] = ((sA.x + sA.y) + (sA.z + sA.w)) + ((sB.x + sB.y) + (sB.z + sB.w));
            bool excl = (mk_sh[j][node] > 0.5f);
            act[r] = valid && !excl;
            if (act[r]) lm = fmaxf(lm, sbv[r]);
        }
        #pragma unroll
        for (int off = 16; off > 0; off >>= 1)
            lm = fmaxf(lm, __shfl_xor_sync(0xFFFFFFFFu, lm, off));

        #pragma unroll
        for (int r = 0; r < 2; r++) {
            pv[r] = 0.f;
            if (act[r]) {
                pv[r] = expf(sbv[r] - lm);
                Sreg[jj[r]] += pv[r];
            }
        }
        #pragma unroll
        for (int off = 16; off > 0; off >>= 1) {
            Sreg[0] += __shfl_xor_sync(0xFFFFFFFFu, Sreg[0], off);
            Sreg[1] += __shfl_xor_sync(0xFFFFFFFFu, Sreg[1], off);
            Sreg[2] += __shfl_xor_sync(0xFFFFFFFFu, Sreg[2], off);
        }
    } else if (w == 2) {
        const float4 x = *(const float4*)&h0_sh[lane * 4];
        float ls[9];
        #pragma unroll
        for (int q = 0; q < 9; q++) {
            const float4 wt = *(const float4*)&g_wab[q * DIM + lane * 4];
            float dq = x.x * wt.x + x.y * wt.y + x.z * wt.z + x.w * wt.w;
            #pragma unroll
            for (int off = 16; off > 0; off >>= 1)
                dq += __shfl_xor_sync(0xFFFFFFFFu, dq, off);
            ls[q] = dq;
        }
        float ml = ls[0];
        #pragma unroll
        for (int q = 1; q < 9; q++) ml = fmaxf(ml, ls[q]);
        if (lane < 3) {
            float e = expf(ls[0 * 3 + lane] - ml) + expf(ls[1 * 3 + lane] - ml)
                    + expf(ls[2 * 3 + lane] - ml);
            E_sh[lane] = e;
        }
    } else if (w == 3 && lane < 3) {
        ((float*)&w2n_sh[0])[lane] = mk_sh[lane][0];
    }
    __syncthreads();

    // ---- phase C ----
    if (w < 2) {
        float E0 = E_sh[0], E1 = E_sh[1], E2 = E_sh[2];
        float Z = E0 * Sreg[0] + E1 * Sreg[1] + E2 * Sreg[2];
        float inv = (Z > 0.f) ? (1.f / Z) : 0.f;
        float Ej[3] = {E0 * inv, E1 * inv, E2 * inv};
        #pragma unroll
        for (int r = 0; r < 2; r++) {
            int p = lane + r * 32;
            const int NP = (w == 0) ? 45 : 48;
            if (p < NP) ((float*)&w2n_sh[nd[r]])[jj[r]] = pv[r] * Ej[jj[r]];
        }
    }
    __syncthreads();

    // ---- register-resident accumulation over this thread's 8 nodes ----
    float4 a0 = make_float4(0.f, 0.f, 0.f, 0.f);
    float4 a1 = a0, a2 = a0;
    #pragma unroll
    for (int v = 0; v < 8; v++) {
        float4 wv = w2n_sh[v * 4 + w];      // LDS.128 broadcast
        float4 x = xs[v];
        a0.x += wv.x * x.x; a0.y += wv.x * x.y; a0.z += wv.x * x.z; a0.w += wv.x * x.w;
        a1.x += wv.y * x.x; a1.y += wv.y * x.y; a1.z += wv.y * x.z; a1.w += wv.y * x.w;
        a2.x += wv.z * x.x; a2.y += wv.z * x.y; a2.z += wv.z * x.z; a2.w += wv.z * x.w;
    }
    *(float4*)&part_sh[w][0][lane * 4] = a0;
    *(float4*)&part_sh[w][1][lane * 4] = a1;
    *(float4*)&part_sh[w][2][lane * 4] = a2;
    __syncthreads();

    // ---- cross-warp sum: 96 threads, float4 wide ----
    if (t < 96) {
        int j = t >> 5;
        int c = (t & 31) * 4;
        float4 s0 = *(const float4*)&part_sh[0][j][c];
        float4 s1 = *(const float4*)&part_sh[1][j][c];
        float4 s2 = *(const float4*)&part_sh[2][j][c];
        float4 s3 = *(const float4*)&part_sh[3][j][c];
        float4 s;
        s.x = (s0.x + s1.x) + (s2.x + s3.x);
        s.y = (s0.y + s1.y) + (s2.y + s3.y);
        s.z = (s0.z + s1.z) + (s2.z + s3.z);
        s.w = (s0.w + s1.w) + (s2.w + s3.w);
        *(float4*)(g_G + (size_t)b * KDIM + j * DIM + c) = s;
    }
}

// ============================================================
// Kernel 2: out = elu( G (8192x384) @ W (384x128) ), fused,
//   double-buffered smem: one barrier per K-stage, LDG for
//   stage s+1 issued before stage-s compute.
// ============================================================
__global__ __launch_bounds__(256) void gemm_elu_kernel(const float* __restrict__ W,
                                                       float* __restrict__ out) {
    __shared__ float Gs[2][32][33];
    __shared__ float Ws[2][32][132];

    const int tid  = threadIdx.x;
    const int w    = tid >> 5;       // warp -> rows w*4..w*4+3
    const int lane = tid & 31;       // lane -> cols lane*4..+3
    const int row0 = blockIdx.x * 32;

    const int gr = tid >> 3, gc = (tid & 7) * 4;
    const float* gsrc = g_G + (size_t)(row0 + gr) * KDIM + gc;
    const int wr = tid >> 5;                 // W row base per v below

    float2 acc[4][2];
    #pragma unroll
    for (int i = 0; i < 4; i++) { acc[i][0] = make_float2(0.f, 0.f); acc[i][1] = make_float2(0.f, 0.f); }

    // stage 0 load
    {
        float4 gx = *(const float4*)gsrc;
        Gs[0][gr][gc + 0] = gx.x; Gs[0][gr][gc + 1] = gx.y;
        Gs[0][gr][gc + 2] = gx.z; Gs[0][gr][gc + 3] = gx.w;
        #pragma unroll
        for (int v = 0; v < 4; v++) {
            int f = tid + v * 256;
            float4 wx = *(const float4*)(W + (size_t)(f >> 5) * DIM + (f & 31) * 4);
            *(float4*)&Ws[0][f >> 5][(f & 31) * 4] = wx;
        }
    }
    __syncthreads();

    #pragma unroll 1
    for (int s = 0; s < 12; s++) {
        const int cur = s & 1;
        const int nxt = cur ^ 1;

        // prefetch stage s+1 into registers (before compute)
        float4 gx;
        float4 wx[4];
        if (s < 11) {
            int k0 = (s + 1) * 32;
            gx = *(const float4*)(gsrc + k0);
            #pragma unroll
            for (int v = 0; v < 4; v++) {
                int f = tid + v * 256;
                wx[v] = *(const float4*)(W + (size_t)(k0 + (f >> 5)) * DIM + (f & 31) * 4);
            }
        }

        // compute stage s
        #pragma unroll
        for (int kk = 0; kk < 32; kk++) {
            float4 bv = *(const float4*)&Ws[cur][kk][lane * 4];
            float2 b01 = make_float2(bv.x, bv.y);
            float2 b23 = make_float2(bv.z, bv.w);
            #pragma unroll
            for (int i = 0; i < 4; i++) {
                float a = Gs[cur][w * 4 + i][kk];         // broadcast
                float2 a2 = make_float2(a, a);
                acc[i][0] = ffma2(a2, b01, acc[i][0]);
                acc[i][1] = ffma2(a2, b23, acc[i][1]);
            }
        }

        // store stage s+1 into other buffer
        if (s < 11) {
            Gs[nxt][gr][gc + 0] = gx.x; Gs[nxt][gr][gc + 1] = gx.y;
            Gs[nxt][gr][gc + 2] = gx.z; Gs[nxt][gr][gc + 3] = gx.w;
            #pragma unroll
            for (int v = 0; v < 4; v++) {
                int f = tid + v * 256;
                *(float4*)&Ws[nxt][f >> 5][(f & 31) * 4] = wx[v];
            }
        }
        __syncthreads();
    }

    #pragma unroll
    for (int i = 0; i < 4; i++) {
        int r = row0 + w * 4 + i;
        float4 v;
        v.x = acc[i][0].x; v.y = acc[i][0].y; v.z = acc[i][1].x; v.w = acc[i][1].y;
        v.x = (v.x > 0.f) ? v.x : expm1f(v.x);
        v.y = (v.y > 0.f) ? v.y : expm1f(v.y);
        v.z = (v.z > 0.f) ? v.z : expm1f(v.z);
        v.w = (v.w > 0.f) ? v.w : expm1f(v.w);
        *(float4*)(out + (size_t)r * DIM + lane * 4) = v;
    }
}

// ============================================================
extern "C" void kernel_launch(void* const* d_in, const int* in_sizes, int n_in,
                              void* d_out, int out_size) {
    const float* h    = (const float*)d_in[0];
    const void*  mask = d_in[1];
    const float* W    = (const float*)d_in[5];
    const float* a    = (const float*)d_in[6];
    float* out = (float*)d_out;

    prep_detect_kernel<<<13, 256>>>((const unsigned int*)mask, W, a);
    attn_kernel<<<BATCH, 128>>>(h, mask);
    gemm_elu_kernel<<<BATCH / 32, 256>>>(W, out);
}